// round 1
// baseline (speedup 1.0000x reference)
#include <cuda_runtime.h>

// Problem constants
#define B_ 8
#define T_ 64
#define N_ 512
#define D_ 64
#define KH_ 8
#define DH_ 8
#define NEG_ (-32767.0f)

// smem layout (floats)
//  H  : 64 x 132  (concat(x,ste); later reused as attention output O, stride 132)
//  Wb : 128 x 64  (weights; reused as S scores stride 69, then W1/W2 stride 64)
//  Qb : 64 x 65   (q; reused as FFN hidden U)
//  KT : 64 x 68   (k transposed: KT[col][t])
//  Vb : 64 x 65
#define H_OFF   0
#define H_STR   132
#define W_OFF   (64 * 132)                 // 8448
#define S_STR   69
#define Q_OFF   (W_OFF + 128 * 64)         // 16640
#define Q_STR   65
#define KT_OFF  (Q_OFF + 64 * 65)          // 20800
#define KT_STR  68
#define V_OFF   (KT_OFF + 64 * 68)         // 25152
#define V_STR   65
#define SMEM_FLOATS (V_OFF + 64 * 65)      // 29312 floats = 117248 B

__global__ __launch_bounds__(256, 1)
void temporal_attn_kernel(
    const float* __restrict__ x,  const float* __restrict__ ste,
    const float* __restrict__ Wq, const float* __restrict__ bq,
    const float* __restrict__ Wk, const float* __restrict__ bk,
    const float* __restrict__ Wv, const float* __restrict__ bv,
    const float* __restrict__ W1, const float* __restrict__ b1,
    const float* __restrict__ W2, const float* __restrict__ b2,
    float* __restrict__ out)
{
    extern __shared__ float sm[];
    float* H  = sm + H_OFF;
    float* Wb = sm + W_OFF;
    float* Qb = sm + Q_OFF;
    float* KT = sm + KT_OFF;
    float* Vb = sm + V_OFF;

    const int tid = threadIdx.x;
    const int bid = blockIdx.x;
    const int n   = bid & (N_ - 1);
    const int b   = bid >> 9;

    // ---- load H = concat(x, ste) for this (b, n): 64 rows x 128 cols ----
    {
        const float* xb  = x   + ((size_t)((size_t)b * T_) * N_ + n) * D_;
        const float* sb  = ste + ((size_t)((size_t)b * T_) * N_ + n) * D_;
        for (int idx = tid; idx < T_ * D_; idx += 256) {
            int t = idx >> 6, f = idx & 63;
            size_t g = (size_t)t * (N_ * D_) + f;
            H[t * H_STR + f]      = xb[g];
            H[t * H_STR + 64 + f] = sb[g];
        }
    }

    // thread tile mapping for 64x64 GEMM phases: 4 rows x 4 interleaved cols
    const int tt = tid >> 4;         // 0..15
    const int jt = tid & 15;         // 0..15
    const int t0 = tt * 4;

    // ---- QKV projections: out = relu(H[64x128] @ W[128x64] + b) ----
    for (int m = 0; m < 3; m++) {
        const float* W    = (m == 0) ? Wq : (m == 1) ? Wk : Wv;
        const float* bias = (m == 0) ? bq : (m == 1) ? bk : bv;
        __syncthreads();   // prior readers of Wb / H done
        for (int idx = tid; idx < 128 * 64; idx += 256) Wb[idx] = W[idx];
        __syncthreads();

        float acc[4][4];
        #pragma unroll
        for (int i = 0; i < 4; i++)
            #pragma unroll
            for (int c = 0; c < 4; c++)
                acc[i][c] = bias[jt + 16 * c];

        #pragma unroll 4
        for (int f = 0; f < 128; f++) {
            float hv[4], wv[4];
            #pragma unroll
            for (int i = 0; i < 4; i++) hv[i] = H[(t0 + i) * H_STR + f];
            #pragma unroll
            for (int c = 0; c < 4; c++) wv[c] = Wb[f * 64 + jt + 16 * c];
            #pragma unroll
            for (int i = 0; i < 4; i++)
                #pragma unroll
                for (int c = 0; c < 4; c++)
                    acc[i][c] = fmaf(hv[i], wv[c], acc[i][c]);
        }

        #pragma unroll
        for (int i = 0; i < 4; i++) {
            #pragma unroll
            for (int c = 0; c < 4; c++) {
                float r = fmaxf(acc[i][c], 0.0f);
                int t = t0 + i, j = jt + 16 * c;
                if (m == 0)      Qb[t * Q_STR + j] = r;
                else if (m == 1) KT[j * KT_STR + t] = r;   // store K transposed
                else             Vb[t * V_STR + j] = r;
            }
        }
    }
    __syncthreads();

    // ---- attention per head (scores buffer S aliases Wb, stride 69) ----
    float* S = Wb;
    const float rsc = 0.3535533905932738f;  // 1/sqrt(8)

    for (int hh = 0; hh < KH_; hh++) {
        const int hc = hh * DH_;

        // scores S[t][s] = (q[t,hc:]·k[s,hc:]) * rsc, causal mask
        for (int i = 0; i < 16; i++) {
            int e = tid + i * 256;
            int t = e >> 6, s = e & 63;
            float a0 = 0.f, a1 = 0.f;
            #pragma unroll
            for (int d0 = 0; d0 < DH_; d0 += 2) {
                a0 = fmaf(Qb[t * Q_STR + hc + d0],     KT[(hc + d0) * KT_STR + s],     a0);
                a1 = fmaf(Qb[t * Q_STR + hc + d0 + 1], KT[(hc + d0 + 1) * KT_STR + s], a1);
            }
            float a = (a0 + a1) * rsc;
            if (s > t) a = NEG_;
            S[t * S_STR + s] = a;
        }
        __syncthreads();

        // softmax over s (rows are independent; stride 69 => conflict-free)
        if (tid < 64) {
            const int t = tid;
            float mx = -1e30f;
            for (int s = 0; s < 64; s++) mx = fmaxf(mx, S[t * S_STR + s]);
            float sum = 0.f;
            for (int s = 0; s < 64; s++) {
                float e = __expf(S[t * S_STR + s] - mx);
                S[t * S_STR + s] = e;
                sum += e;
            }
            float inv = 1.0f / sum;
            for (int s = 0; s < 64; s++) S[t * S_STR + s] *= inv;
        }
        __syncthreads();

        // O[t][hc+d] = sum_s S[t][s] * V[s][hc+d]   (O aliases H, stride 132)
        #pragma unroll
        for (int i = 0; i < 2; i++) {
            int e = tid + i * 256;
            int t = e >> 3, d0 = e & 7;
            int col = hc + d0;
            float a0 = 0.f, a1 = 0.f;
            #pragma unroll 4
            for (int s = 0; s < 64; s += 2) {
                a0 = fmaf(S[t * S_STR + s],     Vb[s * V_STR + col],       a0);
                a1 = fmaf(S[t * S_STR + s + 1], Vb[(s + 1) * V_STR + col], a1);
            }
            H[t * H_STR + col] = a0 + a1;
        }
        __syncthreads();
    }

    // ---- FFN layer 1: U = relu(O @ W1 + b1), U aliases Qb ----
    for (int idx = tid; idx < 64 * 64; idx += 256) Wb[idx] = W1[idx];
    __syncthreads();
    {
        float acc[4][4];
        #pragma unroll
        for (int i = 0; i < 4; i++)
            #pragma unroll
            for (int c = 0; c < 4; c++)
                acc[i][c] = b1[jt + 16 * c];
        #pragma unroll 4
        for (int f = 0; f < 64; f++) {
            float hv[4], wv[4];
            #pragma unroll
            for (int i = 0; i < 4; i++) hv[i] = H[(t0 + i) * H_STR + f];
            #pragma unroll
            for (int c = 0; c < 4; c++) wv[c] = Wb[f * 64 + jt + 16 * c];
            #pragma unroll
            for (int i = 0; i < 4; i++)
                #pragma unroll
                for (int c = 0; c < 4; c++)
                    acc[i][c] = fmaf(hv[i], wv[c], acc[i][c]);
        }
        __syncthreads();  // everyone done reading Qb (as q) long ago; done reading Wb(W1)
        #pragma unroll
        for (int i = 0; i < 4; i++)
            #pragma unroll
            for (int c = 0; c < 4; c++)
                Qb[(t0 + i) * Q_STR + jt + 16 * c] = fmaxf(acc[i][c], 0.0f);
    }
    __syncthreads();

    // ---- FFN layer 2: out = U @ W2 + b2 -> global ----
    for (int idx = tid; idx < 64 * 64; idx += 256) Wb[idx] = W2[idx];
    __syncthreads();
    {
        float acc[4][4];
        #pragma unroll
        for (int i = 0; i < 4; i++)
            #pragma unroll
            for (int c = 0; c < 4; c++)
                acc[i][c] = b2[jt + 16 * c];
        #pragma unroll 4
        for (int f = 0; f < 64; f++) {
            float hv[4], wv[4];
            #pragma unroll
            for (int i = 0; i < 4; i++) hv[i] = Qb[(t0 + i) * Q_STR + f];
            #pragma unroll
            for (int c = 0; c < 4; c++) wv[c] = Wb[f * 64 + jt + 16 * c];
            #pragma unroll
            for (int i = 0; i < 4; i++)
                #pragma unroll
                for (int c = 0; c < 4; c++)
                    acc[i][c] = fmaf(hv[i], wv[c], acc[i][c]);
        }
        #pragma unroll
        for (int i = 0; i < 4; i++) {
            int t = t0 + i;
            float* op = out + (((size_t)b * T_ + t) * N_ + n) * D_;
            #pragma unroll
            for (int c = 0; c < 4; c++)
                op[jt + 16 * c] = acc[i][c];
        }
    }
}

extern "C" void kernel_launch(void* const* d_in, const int* in_sizes, int n_in,
                              void* d_out, int out_size)
{
    (void)in_sizes; (void)n_in; (void)out_size;
    const float* x   = (const float*)d_in[0];
    const float* ste = (const float*)d_in[1];
    const float* Wq  = (const float*)d_in[2];
    const float* bq  = (const float*)d_in[3];
    const float* Wk  = (const float*)d_in[4];
    const float* bk  = (const float*)d_in[5];
    const float* Wv  = (const float*)d_in[6];
    const float* bv  = (const float*)d_in[7];
    const float* W1  = (const float*)d_in[8];
    const float* b1  = (const float*)d_in[9];
    const float* W2  = (const float*)d_in[10];
    const float* b2  = (const float*)d_in[11];
    float* out = (float*)d_out;

    const int smem_bytes = SMEM_FLOATS * sizeof(float);
    static bool attr_set = false;
    if (!attr_set) {
        cudaFuncSetAttribute(temporal_attn_kernel,
                             cudaFuncAttributeMaxDynamicSharedMemorySize,
                             smem_bytes);
        attr_set = true;
    }
    temporal_attn_kernel<<<B_ * N_, 256, smem_bytes>>>(
        x, ste, Wq, bq, Wk, bk, Wv, bv, W1, b1, W2, b2, out);
}

// round 2
// speedup vs baseline: 1.7932x; 1.7932x over previous
#include <cuda_runtime.h>

// Problem constants
#define B_ 8
#define T_ 64
#define N_ 512
#define D_ 64
#define KH_ 8
#define DH_ 8
#define NEG_ (-32767.0f)

// Shared layout (floats):
//   Wt : 64 x 132  (weights transposed [j][f]; QKV stride 132, FFN stride 68) -- SHARED by both problems
//   per problem (x2):
//     H  : 64 x 132 (concat(x,ste); cols 64..127 reused as scores S; cols 0..63 reused as attn output O)
//     Qb : 64 x 68  (q; reused as FFN hidden U)
//     Kb : 64 x 68  (k row-major)
//     Vb : 64 x 68
#define WT_SZ   (64 * 132)                    // 8448
#define PROB_SZ (64 * 132 + 3 * 64 * 68)      // 21504
#define SMEM_FLOATS (WT_SZ + 2 * PROB_SZ)     // 51456 floats = 205824 B
#define H_STR   132
#define QKV_STR 68

__global__ __launch_bounds__(512, 1)
void temporal_attn_kernel(
    const float* __restrict__ x,  const float* __restrict__ ste,
    const float* __restrict__ Wq, const float* __restrict__ bq,
    const float* __restrict__ Wk, const float* __restrict__ bk,
    const float* __restrict__ Wv, const float* __restrict__ bv,
    const float* __restrict__ W1, const float* __restrict__ b1,
    const float* __restrict__ W2, const float* __restrict__ b2,
    float* __restrict__ out)
{
    extern __shared__ float sm[];
    const int tid  = threadIdx.x;
    const int pid  = tid >> 8;           // which of 2 problems in this CTA
    const int ltid = tid & 255;

    const int p = blockIdx.x * 2 + pid;  // global (b,n) index
    const int n = p & (N_ - 1);
    const int b = p >> 9;

    float* Wt = sm;
    float* H  = sm + WT_SZ + pid * PROB_SZ;
    float* Qb = H  + 64 * H_STR;
    float* Kb = Qb + 64 * QKV_STR;
    float* Vb = Kb + 64 * QKV_STR;
    float* S  = H + 64;                  // scores live in H cols 64..127

    // ---- load H = concat(x, ste): 64 rows x 128 cols, float4 ----
    {
        const float* xb = x   + ((size_t)((size_t)b * T_) * N_ + n) * D_;
        const float* sb = ste + ((size_t)((size_t)b * T_) * N_ + n) * D_;
        #pragma unroll
        for (int i = 0; i < 4; i++) {
            int idx = ltid + i * 256;            // 0..1023
            int t = idx >> 4, f4 = (idx & 15) << 2;
            size_t g = (size_t)t * (N_ * D_) + f4;
            *(float4*)&H[t * H_STR + f4]      = *(const float4*)&xb[g];
            *(float4*)&H[t * H_STR + 64 + f4] = *(const float4*)&sb[g];
        }
    }

    // thread tile mapping for 64x64 outputs: 4 rows x 4 interleaved cols
    const int tt = ltid >> 4;            // 0..15
    const int jt = ltid & 15;            // 0..15
    const int t0 = tt * 4;

    // ---- QKV projections: relu(H[64x128] @ W[128x64] + b) ----
    for (int m = 0; m < 3; m++) {
        const float* W    = (m == 0) ? Wq : (m == 1) ? Wk : Wv;
        const float* bias = (m == 0) ? bq : (m == 1) ? bk : bv;
        __syncthreads();                 // previous Wt readers done (also covers H load on m=0)
        for (int idx = tid; idx < 128 * 64; idx += 512) {
            int f = idx >> 6, j = idx & 63;
            Wt[j * 132 + f] = W[idx];    // store transposed
        }
        __syncthreads();

        float acc[4][4];
        #pragma unroll
        for (int c = 0; c < 4; c++) {
            float bb = bias[jt + 16 * c];
            #pragma unroll
            for (int i = 0; i < 4; i++) acc[i][c] = bb;
        }

        #pragma unroll 2
        for (int f = 0; f < 128; f += 4) {
            float4 hv[4], wv[4];
            #pragma unroll
            for (int i = 0; i < 4; i++) hv[i] = *(float4*)&H[(t0 + i) * H_STR + f];
            #pragma unroll
            for (int c = 0; c < 4; c++) wv[c] = *(float4*)&Wt[(jt + 16 * c) * 132 + f];
            #pragma unroll
            for (int i = 0; i < 4; i++)
                #pragma unroll
                for (int c = 0; c < 4; c++) {
                    acc[i][c] = fmaf(hv[i].x, wv[c].x, acc[i][c]);
                    acc[i][c] = fmaf(hv[i].y, wv[c].y, acc[i][c]);
                    acc[i][c] = fmaf(hv[i].z, wv[c].z, acc[i][c]);
                    acc[i][c] = fmaf(hv[i].w, wv[c].w, acc[i][c]);
                }
        }

        float* dst = (m == 0) ? Qb : (m == 1) ? Kb : Vb;
        #pragma unroll
        for (int i = 0; i < 4; i++)
            #pragma unroll
            for (int c = 0; c < 4; c++)
                dst[(t0 + i) * QKV_STR + jt + 16 * c] = fmaxf(acc[i][c], 0.0f);
    }
    __syncthreads();   // Q,K,V visible; H reads (as GEMM input) done -> S may overwrite cols 64..127

    // ---- attention per head ----
    const float rsc = 0.3535533905932738f;   // 1/sqrt(8)

    for (int hh = 0; hh < KH_; hh++) {
        const int hc = hh * DH_;

        // scores: 4x4 tile per thread, q/k as float4 pairs
        {
            float4 qa[4], qb4[4];
            #pragma unroll
            for (int i = 0; i < 4; i++) {
                qa[i]  = *(float4*)&Qb[(t0 + i) * QKV_STR + hc];
                qb4[i] = *(float4*)&Qb[(t0 + i) * QKV_STR + hc + 4];
            }
            float acc[4][4];
            #pragma unroll
            for (int c = 0; c < 4; c++) {
                int s = jt + 16 * c;
                float4 ka = *(float4*)&Kb[s * QKV_STR + hc];
                float4 kb = *(float4*)&Kb[s * QKV_STR + hc + 4];
                #pragma unroll
                for (int i = 0; i < 4; i++) {
                    float a;
                    a = qa[i].x * ka.x;
                    a = fmaf(qa[i].y, ka.y, a);
                    a = fmaf(qa[i].z, ka.z, a);
                    a = fmaf(qa[i].w, ka.w, a);
                    a = fmaf(qb4[i].x, kb.x, a);
                    a = fmaf(qb4[i].y, kb.y, a);
                    a = fmaf(qb4[i].z, kb.z, a);
                    a = fmaf(qb4[i].w, kb.w, a);
                    acc[i][c] = a;
                }
            }
            #pragma unroll
            for (int i = 0; i < 4; i++)
                #pragma unroll
                for (int c = 0; c < 4; c++) {
                    int t = t0 + i, s = jt + 16 * c;
                    float a = acc[i][c] * rsc;
                    if (s > t) a = NEG_;
                    S[t * H_STR + s] = a;
                }
        }
        __syncthreads();

        // softmax: 4 lanes per row, shfl reductions
        {
            const int r  = ltid >> 2;
            const int l4 = ltid & 3;
            float* row = S + r * H_STR;
            float v[16];
            float mx = -1e30f;
            #pragma unroll
            for (int k = 0; k < 16; k++) {
                v[k] = row[l4 + 4 * k];
                mx = fmaxf(mx, v[k]);
            }
            mx = fmaxf(mx, __shfl_xor_sync(0xffffffffu, mx, 1));
            mx = fmaxf(mx, __shfl_xor_sync(0xffffffffu, mx, 2));
            float sum = 0.0f;
            #pragma unroll
            for (int k = 0; k < 16; k++) {
                v[k] = __expf(v[k] - mx);
                sum += v[k];
            }
            sum += __shfl_xor_sync(0xffffffffu, sum, 1);
            sum += __shfl_xor_sync(0xffffffffu, sum, 2);
            float inv = 1.0f / sum;
            #pragma unroll
            for (int k = 0; k < 16; k++) row[l4 + 4 * k] = v[k] * inv;
        }
        __syncthreads();

        // AV: each lane-pair produces one float4 of O; split s-range, shfl-combine
        {
            const int grp = ltid >> 1;          // 0..127
            const int sh  = ltid & 1;           // s-half
            const int t   = grp >> 1;
            const int colb = hc + (grp & 1) * 4;
            const int sb0 = sh * 32;
            float4 acc4 = make_float4(0.f, 0.f, 0.f, 0.f);
            const float* srow = S + t * H_STR + sb0;
            #pragma unroll 2
            for (int s4 = 0; s4 < 32; s4 += 4) {
                float4 sc = *(const float4*)&srow[s4];
                float4 v0 = *(float4*)&Vb[(sb0 + s4 + 0) * QKV_STR + colb];
                float4 v1 = *(float4*)&Vb[(sb0 + s4 + 1) * QKV_STR + colb];
                float4 v2 = *(float4*)&Vb[(sb0 + s4 + 2) * QKV_STR + colb];
                float4 v3 = *(float4*)&Vb[(sb0 + s4 + 3) * QKV_STR + colb];
                acc4.x = fmaf(sc.x, v0.x, acc4.x); acc4.y = fmaf(sc.x, v0.y, acc4.y);
                acc4.z = fmaf(sc.x, v0.z, acc4.z); acc4.w = fmaf(sc.x, v0.w, acc4.w);
                acc4.x = fmaf(sc.y, v1.x, acc4.x); acc4.y = fmaf(sc.y, v1.y, acc4.y);
                acc4.z = fmaf(sc.y, v1.z, acc4.z); acc4.w = fmaf(sc.y, v1.w, acc4.w);
                acc4.x = fmaf(sc.z, v2.x, acc4.x); acc4.y = fmaf(sc.z, v2.y, acc4.y);
                acc4.z = fmaf(sc.z, v2.z, acc4.z); acc4.w = fmaf(sc.z, v2.w, acc4.w);
                acc4.x = fmaf(sc.w, v3.x, acc4.x); acc4.y = fmaf(sc.w, v3.y, acc4.y);
                acc4.z = fmaf(sc.w, v3.z, acc4.z); acc4.w = fmaf(sc.w, v3.w, acc4.w);
            }
            acc4.x += __shfl_xor_sync(0xffffffffu, acc4.x, 1);
            acc4.y += __shfl_xor_sync(0xffffffffu, acc4.y, 1);
            acc4.z += __shfl_xor_sync(0xffffffffu, acc4.z, 1);
            acc4.w += __shfl_xor_sync(0xffffffffu, acc4.w, 1);
            if (sh == 0) *(float4*)&H[t * H_STR + colb] = acc4;
        }
        __syncthreads();
    }

    // ---- FFN layer 1: U = relu(O @ W1 + b1), U -> Qb ----
    for (int idx = tid; idx < 64 * 64; idx += 512) {
        int f = idx >> 6, j = idx & 63;
        Wt[j * QKV_STR + f] = W1[idx];
    }
    __syncthreads();
    {
        float acc[4][4];
        #pragma unroll
        for (int c = 0; c < 4; c++) {
            float bb = b1[jt + 16 * c];
            #pragma unroll
            for (int i = 0; i < 4; i++) acc[i][c] = bb;
        }
        #pragma unroll 2
        for (int f = 0; f < 64; f += 4) {
            float4 hv[4], wv[4];
            #pragma unroll
            for (int i = 0; i < 4; i++) hv[i] = *(float4*)&H[(t0 + i) * H_STR + f];
            #pragma unroll
            for (int c = 0; c < 4; c++) wv[c] = *(float4*)&Wt[(jt + 16 * c) * QKV_STR + f];
            #pragma unroll
            for (int i = 0; i < 4; i++)
                #pragma unroll
                for (int c = 0; c < 4; c++) {
                    acc[i][c] = fmaf(hv[i].x, wv[c].x, acc[i][c]);
                    acc[i][c] = fmaf(hv[i].y, wv[c].y, acc[i][c]);
                    acc[i][c] = fmaf(hv[i].z, wv[c].z, acc[i][c]);
                    acc[i][c] = fmaf(hv[i].w, wv[c].w, acc[i][c]);
                }
        }
        #pragma unroll
        for (int i = 0; i < 4; i++)
            #pragma unroll
            for (int c = 0; c < 4; c++)
                Qb[(t0 + i) * QKV_STR + jt + 16 * c] = fmaxf(acc[i][c], 0.0f);
    }
    __syncthreads();    // W1 reads done + U visible

    // ---- FFN layer 2: out = U @ W2 + b2 -> global ----
    for (int idx = tid; idx < 64 * 64; idx += 512) {
        int f = idx >> 6, j = idx & 63;
        Wt[j * QKV_STR + f] = W2[idx];
    }
    __syncthreads();
    {
        float acc[4][4];
        #pragma unroll
        for (int c = 0; c < 4; c++) {
            float bb = b2[jt + 16 * c];
            #pragma unroll
            for (int i = 0; i < 4; i++) acc[i][c] = bb;
        }
        #pragma unroll 2
        for (int f = 0; f < 64; f += 4) {
            float4 hv[4], wv[4];
            #pragma unroll
            for (int i = 0; i < 4; i++) hv[i] = *(float4*)&Qb[(t0 + i) * QKV_STR + f];
            #pragma unroll
            for (int c = 0; c < 4; c++) wv[c] = *(float4*)&Wt[(jt + 16 * c) * QKV_STR + f];
            #pragma unroll
            for (int i = 0; i < 4; i++)
                #pragma unroll
                for (int c = 0; c < 4; c++) {
                    acc[i][c] = fmaf(hv[i].x, wv[c].x, acc[i][c]);
                    acc[i][c] = fmaf(hv[i].y, wv[c].y, acc[i][c]);
                    acc[i][c] = fmaf(hv[i].z, wv[c].z, acc[i][c]);
                    acc[i][c] = fmaf(hv[i].w, wv[c].w, acc[i][c]);
                }
        }
        #pragma unroll
        for (int i = 0; i < 4; i++) {
            int t = t0 + i;
            float* op = out + (((size_t)b * T_ + t) * N_ + n) * D_;
            #pragma unroll
            for (int c = 0; c < 4; c++)
                op[jt + 16 * c] = acc[i][c];
        }
    }
}

extern "C" void kernel_launch(void* const* d_in, const int* in_sizes, int n_in,
                              void* d_out, int out_size)
{
    (void)in_sizes; (void)n_in; (void)out_size;
    const float* x   = (const float*)d_in[0];
    const float* ste = (const float*)d_in[1];
    const float* Wq  = (const float*)d_in[2];
    const float* bq  = (const float*)d_in[3];
    const float* Wk  = (const float*)d_in[4];
    const float* bk  = (const float*)d_in[5];
    const float* Wv  = (const float*)d_in[6];
    const float* bv  = (const float*)d_in[7];
    const float* W1  = (const float*)d_in[8];
    const float* b1  = (const float*)d_in[9];
    const float* W2  = (const float*)d_in[10];
    const float* b2  = (const float*)d_in[11];
    float* out = (float*)d_out;

    const int smem_bytes = SMEM_FLOATS * sizeof(float);   // 205824
    static bool attr_set = false;
    if (!attr_set) {
        cudaFuncSetAttribute(temporal_attn_kernel,
                             cudaFuncAttributeMaxDynamicSharedMemorySize,
                             smem_bytes);
        attr_set = true;
    }
    temporal_attn_kernel<<<(B_ * N_) / 2, 512, smem_bytes>>>(
        x, ste, Wq, bq, Wk, bk, Wv, bv, W1, b1, W2, b2, out);
}

// round 4
// speedup vs baseline: 2.0408x; 1.1381x over previous
#include <cuda_runtime.h>
#include <cstdint>

// Problem constants
#define B_ 8
#define T_ 64
#define N_ 512
#define D_ 64
#define KH_ 8
#define NEG_ (-32767.0f)

// smem (floats), per problem:
//   H  : 64 x 132 (concat(x,ste); cols 64..127 reused as scores S; cols 0..63 reused as attn output O)
//   Qf : 64 x 68  (q; reused as FFN hidden U)
//   Kf : 64 x 68
//   Vf : 64 x 68
#define H_STR   132
#define QKV_STR 68
#define PROB_SZ (64 * H_STR + 3 * 64 * QKV_STR)   // 21504 floats
#define SMEM_FLOATS (2 * PROB_SZ)                 // 43008 floats = 172032 B

// ---- tf32 helpers ----
__device__ __forceinline__ uint32_t tf32_hi(float v) {
    uint32_t h;
    asm("cvt.rna.tf32.f32 %0, %1;" : "=r"(h) : "f"(v));
    return h;
}
__device__ __forceinline__ void tf32_split(float v, uint32_t& hi, uint32_t& lo) {
    hi = tf32_hi(v);
    float l = v - __uint_as_float(hi);
    lo = tf32_hi(l);
}
__device__ __forceinline__ void mma8(float c[4], const uint32_t a[4], const uint32_t b[2]) {
    asm volatile(
        "mma.sync.aligned.m16n8k8.row.col.f32.tf32.tf32.f32 "
        "{%0,%1,%2,%3}, {%4,%5,%6,%7}, {%8,%9}, {%0,%1,%2,%3};"
        : "+f"(c[0]), "+f"(c[1]), "+f"(c[2]), "+f"(c[3])
        : "r"(a[0]), "r"(a[1]), "r"(a[2]), "r"(a[3]), "r"(b[0]), "r"(b[1]));
}

// 64xN-slab GEMM accumulate: acc[4][4] covers rows mtile*16..+16, cols nhalf*32..+32
// A: smem fp32 (stride ASTR), W: global fp32 [k][64] row-major. 3-term tf32 split.
template<int KSTEPS, int ASTR>
__device__ __forceinline__ void mma_gemm64(const float* __restrict__ A,
                                           const float* __restrict__ W,
                                           float acc[4][4],
                                           int mtile, int nhalf, int g, int tq)
{
    const float* Ab = A + mtile * 16 * ASTR;
    #pragma unroll
    for (int kk = 0; kk < KSTEPS; kk++) {
        const int k0 = kk * 8;
        float a0 = Ab[g * ASTR + k0 + tq];
        float a1 = Ab[(g + 8) * ASTR + k0 + tq];
        float a2 = Ab[g * ASTR + k0 + tq + 4];
        float a3 = Ab[(g + 8) * ASTR + k0 + tq + 4];
        uint32_t ah[4], al[4];
        tf32_split(a0, ah[0], al[0]);
        tf32_split(a1, ah[1], al[1]);
        tf32_split(a2, ah[2], al[2]);
        tf32_split(a3, ah[3], al[3]);

        // load all B fragments for this k-step first (ILP), then mma
        float bv0[4], bv1[4];
        #pragma unroll
        for (int nt = 0; nt < 4; nt++) {
            const float* Wb = W + k0 * 64 + nhalf * 32 + nt * 8;
            bv0[nt] = Wb[tq * 64 + g];
            bv1[nt] = Wb[(tq + 4) * 64 + g];
        }
        #pragma unroll
        for (int nt = 0; nt < 4; nt++) {
            uint32_t bh[2], bl[2];
            tf32_split(bv0[nt], bh[0], bl[0]);
            tf32_split(bv1[nt], bh[1], bl[1]);
            mma8(acc[nt], ah, bh);
            mma8(acc[nt], ah, bl);
            mma8(acc[nt], al, bh);
        }
    }
}

__global__ __launch_bounds__(512, 1)
void temporal_attn_kernel(
    const float* __restrict__ x,  const float* __restrict__ ste,
    const float* __restrict__ Wq, const float* __restrict__ bq,
    const float* __restrict__ Wk, const float* __restrict__ bk,
    const float* __restrict__ Wv, const float* __restrict__ bv,
    const float* __restrict__ W1, const float* __restrict__ b1,
    const float* __restrict__ W2, const float* __restrict__ b2,
    float* __restrict__ out)
{
    extern __shared__ float sm[];
    const int tid  = threadIdx.x;
    const int pid  = tid >> 8;           // which of 2 problems
    const int ltid = tid & 255;

    const int p = blockIdx.x * 2 + pid;
    const int n = p & (N_ - 1);
    const int b = p >> 9;

    float* H  = sm + pid * PROB_SZ;
    float* Qf = H  + 64 * H_STR;
    float* Kf = Qf + 64 * QKV_STR;
    float* Vf = Kf + 64 * QKV_STR;
    float* S  = H + 64;                  // scores overlay: H cols 64..127

    // ---- load H = concat(x, ste): 64 x 128, float4 ----
    {
        const float* xb = x   + ((size_t)((size_t)b * T_) * N_ + n) * D_;
        const float* sb = ste + ((size_t)((size_t)b * T_) * N_ + n) * D_;
        #pragma unroll
        for (int i = 0; i < 4; i++) {
            int idx = ltid + i * 256;            // 0..1023
            int t = idx >> 4, f4 = (idx & 15) << 2;
            size_t g = (size_t)t * (N_ * D_) + f4;
            *(float4*)&H[t * H_STR + f4]      = *(const float4*)&xb[g];
            *(float4*)&H[t * H_STR + 64 + f4] = *(const float4*)&sb[g];
        }
    }
    __syncthreads();

    // ---- QKV projections via tf32 mma: relu(H[64x128] @ W[128x64] + b) ----
    const int lane  = tid & 31;
    const int wl    = (tid >> 5) & 7;    // warp within problem (0..7)
    const int g     = lane >> 2;
    const int tq    = lane & 3;
    const int mtile = wl & 3;
    const int nhalf = wl >> 2;

    #pragma unroll 1
    for (int m = 0; m < 3; m++) {
        const float* W    = (m == 0) ? Wq : (m == 1) ? Wk : Wv;
        const float* bias = (m == 0) ? bq : (m == 1) ? bk : bv;
        float* dst        = (m == 0) ? Qf : (m == 1) ? Kf : Vf;

        float acc[4][4];
        #pragma unroll
        for (int i = 0; i < 4; i++)
            #pragma unroll
            for (int j = 0; j < 4; j++) acc[i][j] = 0.0f;

        mma_gemm64<16, H_STR>(H, W, acc, mtile, nhalf, g, tq);

        #pragma unroll
        for (int nt = 0; nt < 4; nt++) {
            int j0 = nhalf * 32 + nt * 8 + 2 * tq;
            float bj0 = bias[j0], bj1 = bias[j0 + 1];
            int r0 = mtile * 16 + g;
            dst[r0 * QKV_STR + j0]           = fmaxf(acc[nt][0] + bj0, 0.0f);
            dst[r0 * QKV_STR + j0 + 1]       = fmaxf(acc[nt][1] + bj1, 0.0f);
            dst[(r0 + 8) * QKV_STR + j0]     = fmaxf(acc[nt][2] + bj0, 0.0f);
            dst[(r0 + 8) * QKV_STR + j0 + 1] = fmaxf(acc[nt][3] + bj1, 0.0f);
        }
    }
    __syncthreads();   // Q,K,V visible; H A-reads done -> S may overwrite cols 64..127

    // ---- attention per head (SIMT fp32, proven round-2 code) ----
    const int tt = ltid >> 4;
    const int jt = ltid & 15;
    const int t0 = tt * 4;
    const float rsc = 0.3535533905932738f;   // 1/sqrt(8)

    for (int hh = 0; hh < KH_; hh++) {
        const int hc = hh * 8;
        {
            float4 qa[4], qb4[4];
            #pragma unroll
            for (int i = 0; i < 4; i++) {
                qa[i]  = *(float4*)&Qf[(t0 + i) * QKV_STR + hc];
                qb4[i] = *(float4*)&Qf[(t0 + i) * QKV_STR + hc + 4];
            }
            float acc[4][4];
            #pragma unroll
            for (int c = 0; c < 4; c++) {
                int s = jt + 16 * c;
                float4 ka = *(float4*)&Kf[s * QKV_STR + hc];
                float4 kb = *(float4*)&Kf[s * QKV_STR + hc + 4];
                #pragma unroll
                for (int i = 0; i < 4; i++) {
                    float a;
                    a = qa[i].x * ka.x;
                    a = fmaf(qa[i].y, ka.y, a);
                    a = fmaf(qa[i].z, ka.z, a);
                    a = fmaf(qa[i].w, ka.w, a);
                    a = fmaf(qb4[i].x, kb.x, a);
                    a = fmaf(qb4[i].y, kb.y, a);
                    a = fmaf(qb4[i].z, kb.z, a);
                    a = fmaf(qb4[i].w, kb.w, a);
                    acc[i][c] = a;
                }
            }
            #pragma unroll
            for (int i = 0; i < 4; i++)
                #pragma unroll
                for (int c = 0; c < 4; c++) {
                    int t = t0 + i, s = jt + 16 * c;
                    float a = acc[i][c] * rsc;
                    if (s > t) a = NEG_;
                    S[t * H_STR + s] = a;
                }
        }
        __syncthreads();
        {
            const int r  = ltid >> 2;
            const int l4 = ltid & 3;
            float* row = S + r * H_STR;
            float v[16];
            float mx = -1e30f;
            #pragma unroll
            for (int k = 0; k < 16; k++) { v[k] = row[l4 + 4 * k]; mx = fmaxf(mx, v[k]); }
            mx = fmaxf(mx, __shfl_xor_sync(0xffffffffu, mx, 1));
            mx = fmaxf(mx, __shfl_xor_sync(0xffffffffu, mx, 2));
            float sum = 0.0f;
            #pragma unroll
            for (int k = 0; k < 16; k++) { v[k] = __expf(v[k] - mx); sum += v[k]; }
            sum += __shfl_xor_sync(0xffffffffu, sum, 1);
            sum += __shfl_xor_sync(0xffffffffu, sum, 2);
            float inv = 1.0f / sum;
            #pragma unroll
            for (int k = 0; k < 16; k++) row[l4 + 4 * k] = v[k] * inv;
        }
        __syncthreads();
        {
            const int grp = ltid >> 1;
            const int sh  = ltid & 1;
            const int t   = grp >> 1;
            const int colb = hc + (grp & 1) * 4;
            const int sb0 = sh * 32;
            float4 a4 = make_float4(0.f, 0.f, 0.f, 0.f);
            const float* srow = S + t * H_STR + sb0;
            #pragma unroll 2
            for (int s4 = 0; s4 < 32; s4 += 4) {
                float4 sc = *(const float4*)&srow[s4];
                float4 v0 = *(float4*)&Vf[(sb0 + s4 + 0) * QKV_STR + colb];
                float4 v1 = *(float4*)&Vf[(sb0 + s4 + 1) * QKV_STR + colb];
                float4 v2 = *(float4*)&Vf[(sb0 + s4 + 2) * QKV_STR + colb];
                float4 v3 = *(float4*)&Vf[(sb0 + s4 + 3) * QKV_STR + colb];
                a4.x = fmaf(sc.x, v0.x, a4.x); a4.y = fmaf(sc.x, v0.y, a4.y);
                a4.z = fmaf(sc.x, v0.z, a4.z); a4.w = fmaf(sc.x, v0.w, a4.w);
                a4.x = fmaf(sc.y, v1.x, a4.x); a4.y = fmaf(sc.y, v1.y, a4.y);
                a4.z = fmaf(sc.y, v1.z, a4.z); a4.w = fmaf(sc.y, v1.w, a4.w);
                a4.x = fmaf(sc.z, v2.x, a4.x); a4.y = fmaf(sc.z, v2.y, a4.y);
                a4.z = fmaf(sc.z, v2.z, a4.z); a4.w = fmaf(sc.z, v2.w, a4.w);
                a4.x = fmaf(sc.w, v3.x, a4.x); a4.y = fmaf(sc.w, v3.y, a4.y);
                a4.z = fmaf(sc.w, v3.z, a4.z); a4.w = fmaf(sc.w, v3.w, a4.w);
            }
            a4.x += __shfl_xor_sync(0xffffffffu, a4.x, 1);
            a4.y += __shfl_xor_sync(0xffffffffu, a4.y, 1);
            a4.z += __shfl_xor_sync(0xffffffffu, a4.z, 1);
            a4.w += __shfl_xor_sync(0xffffffffu, a4.w, 1);
            if (sh == 0) *(float4*)&H[t * H_STR + colb] = a4;
        }
        __syncthreads();
    }

    // ---- FFN layer 1 via mma: U = relu(O @ W1 + b1) -> Qf ----
    {
        float acc[4][4];
        #pragma unroll
        for (int i = 0; i < 4; i++)
            #pragma unroll
            for (int j = 0; j < 4; j++) acc[i][j] = 0.0f;

        mma_gemm64<8, H_STR>(H, W1, acc, mtile, nhalf, g, tq);

        __syncthreads();   // all reads of Qf (as q) done long ago; O reads done
        #pragma unroll
        for (int nt = 0; nt < 4; nt++) {
            int j0 = nhalf * 32 + nt * 8 + 2 * tq;
            float bj0 = b1[j0], bj1 = b1[j0 + 1];
            int r0 = mtile * 16 + g;
            Qf[r0 * QKV_STR + j0]           = fmaxf(acc[nt][0] + bj0, 0.0f);
            Qf[r0 * QKV_STR + j0 + 1]       = fmaxf(acc[nt][1] + bj1, 0.0f);
            Qf[(r0 + 8) * QKV_STR + j0]     = fmaxf(acc[nt][2] + bj0, 0.0f);
            Qf[(r0 + 8) * QKV_STR + j0 + 1] = fmaxf(acc[nt][3] + bj1, 0.0f);
        }
    }
    __syncthreads();

    // ---- FFN layer 2 via mma: out = U @ W2 + b2 -> global ----
    {
        float acc[4][4];
        #pragma unroll
        for (int i = 0; i < 4; i++)
            #pragma unroll
            for (int j = 0; j < 4; j++) acc[i][j] = 0.0f;

        mma_gemm64<8, QKV_STR>(Qf, W2, acc, mtile, nhalf, g, tq);

        #pragma unroll
        for (int nt = 0; nt < 4; nt++) {
            int j0 = nhalf * 32 + nt * 8 + 2 * tq;
            float bj0 = b2[j0], bj1 = b2[j0 + 1];
            int r0 = mtile * 16 + g;
            float* o0 = out + (((size_t)b * T_ + r0)     * N_ + n) * D_ + j0;
            float* o1 = out + (((size_t)b * T_ + r0 + 8) * N_ + n) * D_ + j0;
            o0[0] = acc[nt][0] + bj0;
            o0[1] = acc[nt][1] + bj1;
            o1[0] = acc[nt][2] + bj0;
            o1[1] = acc[nt][3] + bj1;
        }
    }
}

extern "C" void kernel_launch(void* const* d_in, const int* in_sizes, int n_in,
                              void* d_out, int out_size)
{
    (void)in_sizes; (void)n_in; (void)out_size;
    const float* x   = (const float*)d_in[0];
    const float* ste = (const float*)d_in[1];
    const float* Wq  = (const float*)d_in[2];
    const float* bq  = (const float*)d_in[3];
    const float* Wk  = (const float*)d_in[4];
    const float* bk  = (const float*)d_in[5];
    const float* Wv  = (const float*)d_in[6];
    const float* bv  = (const float*)d_in[7];
    const float* W1  = (const float*)d_in[8];
    const float* b1  = (const float*)d_in[9];
    const float* W2  = (const float*)d_in[10];
    const float* b2  = (const float*)d_in[11];
    float* out = (float*)d_out;

    const int smem_bytes = SMEM_FLOATS * sizeof(float);   // 172032
    static bool attr_set = false;
    if (!attr_set) {
        cudaFuncSetAttribute(temporal_attn_kernel,
                             cudaFuncAttributeMaxDynamicSharedMemorySize,
                             smem_bytes);
        attr_set = true;
    }
    temporal_attn_kernel<<<(B_ * N_) / 2, 512, smem_bytes>>>(
        x, ste, Wq, bq, Wk, bk, Wv, bv, W1, b1, W2, b2, out);
}

// round 5
// speedup vs baseline: 2.7583x; 1.3515x over previous
#include <cuda_runtime.h>
#include <cstdint>

// Problem constants
#define B_ 8
#define T_ 64
#define N_ 512
#define D_ 64
#define KH_ 8
#define NEG_ (-32767.0f)

// smem (floats), per problem:
//   H  : 64 x 132 (concat(x,ste); cols 64..127 reused as score buf S0; cols 0..63 reused as attn out O)
//   Qf : 64 x 68  (q; reused as FFN hidden U)
//   Kf : 64 x 68
//   Vf : 64 x 68
//   S1 : 64 x 68  (second score buffer for head-pair processing)
#define H_STR   132
#define QKV_STR 68
#define S1_STR  68
#define PROB_SZ (64 * H_STR + 4 * 64 * QKV_STR)   // 25856 floats
#define SMEM_FLOATS (2 * PROB_SZ)                 // 51712 floats = 206848 B

// ---- tf32 helpers ----
__device__ __forceinline__ uint32_t tf32_hi(float v) {
    uint32_t h;
    asm("cvt.rna.tf32.f32 %0, %1;" : "=r"(h) : "f"(v));
    return h;
}
__device__ __forceinline__ void tf32_split(float v, uint32_t& hi, uint32_t& lo) {
    hi = tf32_hi(v);
    float l = v - __uint_as_float(hi);
    lo = tf32_hi(l);
}
__device__ __forceinline__ void mma8(float c[4], const uint32_t a[4], const uint32_t b[2]) {
    asm volatile(
        "mma.sync.aligned.m16n8k8.row.col.f32.tf32.tf32.f32 "
        "{%0,%1,%2,%3}, {%4,%5,%6,%7}, {%8,%9}, {%0,%1,%2,%3};"
        : "+f"(c[0]), "+f"(c[1]), "+f"(c[2]), "+f"(c[3])
        : "r"(a[0]), "r"(a[1]), "r"(a[2]), "r"(a[3]), "r"(b[0]), "r"(b[1]));
}

// 64xN-slab GEMM accumulate: acc[4][4] covers rows mtile*16..+16, cols nhalf*32..+32
// A: smem fp32 (stride ASTR), W: global fp32 [k][64] row-major. 3-term tf32 split.
template<int KSTEPS, int ASTR>
__device__ __forceinline__ void mma_gemm64(const float* __restrict__ A,
                                           const float* __restrict__ W,
                                           float acc[4][4],
                                           int mtile, int nhalf, int g, int tq)
{
    const float* Ab = A + mtile * 16 * ASTR;
    #pragma unroll
    for (int kk = 0; kk < KSTEPS; kk++) {
        const int k0 = kk * 8;
        float a0 = Ab[g * ASTR + k0 + tq];
        float a1 = Ab[(g + 8) * ASTR + k0 + tq];
        float a2 = Ab[g * ASTR + k0 + tq + 4];
        float a3 = Ab[(g + 8) * ASTR + k0 + tq + 4];
        uint32_t ah[4], al[4];
        tf32_split(a0, ah[0], al[0]);
        tf32_split(a1, ah[1], al[1]);
        tf32_split(a2, ah[2], al[2]);
        tf32_split(a3, ah[3], al[3]);

        float bv0[4], bv1[4];
        #pragma unroll
        for (int nt = 0; nt < 4; nt++) {
            const float* Wb = W + k0 * 64 + nhalf * 32 + nt * 8;
            bv0[nt] = Wb[tq * 64 + g];
            bv1[nt] = Wb[(tq + 4) * 64 + g];
        }
        #pragma unroll
        for (int nt = 0; nt < 4; nt++) {
            uint32_t bh[2], bl[2];
            tf32_split(bv0[nt], bh[0], bl[0]);
            tf32_split(bv1[nt], bh[1], bl[1]);
            mma8(acc[nt], ah, bh);
            mma8(acc[nt], ah, bl);
            mma8(acc[nt], al, bh);
        }
    }
}

// softmax of one 64-wide row with 4 cooperating lanes (lane group l4 = lane&3)
__device__ __forceinline__ void softmax_row(float* __restrict__ row, int l4) {
    float v[16];
    float mx = -1e30f;
    #pragma unroll
    for (int k = 0; k < 16; k++) { v[k] = row[l4 + 4 * k]; mx = fmaxf(mx, v[k]); }
    mx = fmaxf(mx, __shfl_xor_sync(0xffffffffu, mx, 1));
    mx = fmaxf(mx, __shfl_xor_sync(0xffffffffu, mx, 2));
    float sum = 0.0f;
    #pragma unroll
    for (int k = 0; k < 16; k++) { v[k] = __expf(v[k] - mx); sum += v[k]; }
    sum += __shfl_xor_sync(0xffffffffu, sum, 1);
    sum += __shfl_xor_sync(0xffffffffu, sum, 2);
    float inv = 1.0f / sum;
    #pragma unroll
    for (int k = 0; k < 16; k++) row[l4 + 4 * k] = v[k] * inv;
}

__global__ __launch_bounds__(512, 1)
void temporal_attn_kernel(
    const float* __restrict__ x,  const float* __restrict__ ste,
    const float* __restrict__ Wq, const float* __restrict__ bq,
    const float* __restrict__ Wk, const float* __restrict__ bk,
    const float* __restrict__ Wv, const float* __restrict__ bv,
    const float* __restrict__ W1, const float* __restrict__ b1,
    const float* __restrict__ W2, const float* __restrict__ b2,
    float* __restrict__ out)
{
    extern __shared__ float sm[];
    const int tid  = threadIdx.x;
    const int pid  = tid >> 8;           // which of 2 problems
    const int ltid = tid & 255;

    const int p = blockIdx.x * 2 + pid;
    const int n = p & (N_ - 1);
    const int b = p >> 9;

    float* H  = sm + pid * PROB_SZ;
    float* Qf = H  + 64 * H_STR;
    float* Kf = Qf + 64 * QKV_STR;
    float* Vf = Kf + 64 * QKV_STR;
    float* S1 = Vf + 64 * QKV_STR;
    float* S0 = H + 64;                  // score buf 0: H cols 64..127 (stride 132)

    // ---- load H = concat(x, ste): 64 x 128, float4 ----
    {
        const float* xb = x   + ((size_t)((size_t)b * T_) * N_ + n) * D_;
        const float* sb = ste + ((size_t)((size_t)b * T_) * N_ + n) * D_;
        #pragma unroll
        for (int i = 0; i < 4; i++) {
            int idx = ltid + i * 256;            // 0..1023
            int t = idx >> 4, f4 = (idx & 15) << 2;
            size_t g = (size_t)t * (N_ * D_) + f4;
            *(float4*)&H[t * H_STR + f4]      = *(const float4*)&xb[g];
            *(float4*)&H[t * H_STR + 64 + f4] = *(const float4*)&sb[g];
        }
    }
    __syncthreads();

    // warp/lane mapping
    const int lane  = tid & 31;
    const int wl    = (tid >> 5) & 7;    // warp within problem (0..7)
    const int g     = lane >> 2;
    const int tq    = lane & 3;
    const int mtile = wl & 3;
    const int nhalf = wl >> 2;
    const int hsel  = wl >> 2;           // head-of-pair select for attention

    // ---- QKV projections via tf32 mma: relu(H[64x128] @ W[128x64] + b) ----
    #pragma unroll 1
    for (int m = 0; m < 3; m++) {
        const float* W    = (m == 0) ? Wq : (m == 1) ? Wk : Wv;
        const float* bias = (m == 0) ? bq : (m == 1) ? bk : bv;
        float* dst        = (m == 0) ? Qf : (m == 1) ? Kf : Vf;

        float acc[4][4];
        #pragma unroll
        for (int i = 0; i < 4; i++)
            #pragma unroll
            for (int j = 0; j < 4; j++) acc[i][j] = 0.0f;

        mma_gemm64<16, H_STR>(H, W, acc, mtile, nhalf, g, tq);

        #pragma unroll
        for (int nt = 0; nt < 4; nt++) {
            int j0 = nhalf * 32 + nt * 8 + 2 * tq;
            float bj0 = bias[j0], bj1 = bias[j0 + 1];
            int r0 = mtile * 16 + g;
            dst[r0 * QKV_STR + j0]           = fmaxf(acc[nt][0] + bj0, 0.0f);
            dst[r0 * QKV_STR + j0 + 1]       = fmaxf(acc[nt][1] + bj1, 0.0f);
            dst[(r0 + 8) * QKV_STR + j0]     = fmaxf(acc[nt][2] + bj0, 0.0f);
            dst[(r0 + 8) * QKV_STR + j0 + 1] = fmaxf(acc[nt][3] + bj1, 0.0f);
        }
    }
    __syncthreads();   // Q,K,V visible; H A-reads done -> S0 may overwrite cols 64..127

    // ---- attention via tf32 mma, 2 heads per pass ----
    const float rsc = 0.3535533905932738f;   // 1/sqrt(8)
    const int r0m = mtile * 16;

    #pragma unroll 1
    for (int hp = 0; hp < 4; hp++) {
        const int head = hp * 2 + hsel;
        const int hc   = head * 8;
        float* Sb      = hsel ? S1 : S0;
        const int sst  = hsel ? S1_STR : H_STR;

        // scores: S[t][s] = (Q_h @ K_h^T) * rsc, causal mask
        {
            uint32_t ah[4], al[4];
            tf32_split(Qf[(r0m + g)     * QKV_STR + hc + tq],     ah[0], al[0]);
            tf32_split(Qf[(r0m + g + 8) * QKV_STR + hc + tq],     ah[1], al[1]);
            tf32_split(Qf[(r0m + g)     * QKV_STR + hc + tq + 4], ah[2], al[2]);
            tf32_split(Qf[(r0m + g + 8) * QKV_STR + hc + tq + 4], ah[3], al[3]);
            const int ta = r0m + g, tb = ta + 8;
            #pragma unroll
            for (int nt = 0; nt < 8; nt++) {
                const int n0 = nt * 8;
                uint32_t bh[2], bl[2];
                tf32_split(Kf[(n0 + g) * QKV_STR + hc + tq],     bh[0], bl[0]);
                tf32_split(Kf[(n0 + g) * QKV_STR + hc + tq + 4], bh[1], bl[1]);
                float c[4] = {0.f, 0.f, 0.f, 0.f};
                mma8(c, ah, bh);
                mma8(c, ah, bl);
                mma8(c, al, bh);
                const int s0 = n0 + 2 * tq;
                float v0 = (s0     > ta) ? NEG_ : c[0] * rsc;
                float v1 = (s0 + 1 > ta) ? NEG_ : c[1] * rsc;
                float v2 = (s0     > tb) ? NEG_ : c[2] * rsc;
                float v3 = (s0 + 1 > tb) ? NEG_ : c[3] * rsc;
                *(float2*)&Sb[ta * sst + s0] = make_float2(v0, v1);
                *(float2*)&Sb[tb * sst + s0] = make_float2(v2, v3);
            }
        }
        __syncthreads();

        // softmax: 256 threads per problem, each handles row r2 of BOTH buffers
        {
            const int r2 = ltid >> 2, l4 = ltid & 3;
            softmax_row(S0 + r2 * H_STR, l4);
            softmax_row(S1 + r2 * S1_STR, l4);
        }
        __syncthreads();

        // AV: O[t][hc..hc+8] = P @ V_h  (m16n8k8, 8 k-steps over s)
        {
            float c[4] = {0.f, 0.f, 0.f, 0.f};
            #pragma unroll
            for (int kk = 0; kk < 8; kk++) {
                const int k0 = kk * 8;
                uint32_t ah[4], al[4], bh[2], bl[2];
                tf32_split(Sb[(r0m + g)     * sst + k0 + tq],     ah[0], al[0]);
                tf32_split(Sb[(r0m + g + 8) * sst + k0 + tq],     ah[1], al[1]);
                tf32_split(Sb[(r0m + g)     * sst + k0 + tq + 4], ah[2], al[2]);
                tf32_split(Sb[(r0m + g + 8) * sst + k0 + tq + 4], ah[3], al[3]);
                tf32_split(Vf[(k0 + tq)     * QKV_STR + hc + g],  bh[0], bl[0]);
                tf32_split(Vf[(k0 + tq + 4) * QKV_STR + hc + g],  bh[1], bl[1]);
                mma8(c, ah, bh);
                mma8(c, ah, bl);
                mma8(c, al, bh);
            }
            *(float2*)&H[(r0m + g)     * H_STR + hc + 2 * tq] = make_float2(c[0], c[1]);
            *(float2*)&H[(r0m + g + 8) * H_STR + hc + 2 * tq] = make_float2(c[2], c[3]);
        }
        __syncthreads();
    }

    // ---- FFN layer 1 via mma: U = relu(O @ W1 + b1) -> Qf ----
    {
        float acc[4][4];
        #pragma unroll
        for (int i = 0; i < 4; i++)
            #pragma unroll
            for (int j = 0; j < 4; j++) acc[i][j] = 0.0f;

        mma_gemm64<8, H_STR>(H, W1, acc, mtile, nhalf, g, tq);

        __syncthreads();   // all reads of Qf (as q) done; O reads done
        #pragma unroll
        for (int nt = 0; nt < 4; nt++) {
            int j0 = nhalf * 32 + nt * 8 + 2 * tq;
            float bj0 = b1[j0], bj1 = b1[j0 + 1];
            int r0 = mtile * 16 + g;
            Qf[r0 * QKV_STR + j0]           = fmaxf(acc[nt][0] + bj0, 0.0f);
            Qf[r0 * QKV_STR + j0 + 1]       = fmaxf(acc[nt][1] + bj1, 0.0f);
            Qf[(r0 + 8) * QKV_STR + j0]     = fmaxf(acc[nt][2] + bj0, 0.0f);
            Qf[(r0 + 8) * QKV_STR + j0 + 1] = fmaxf(acc[nt][3] + bj1, 0.0f);
        }
    }
    __syncthreads();

    // ---- FFN layer 2 via mma: out = U @ W2 + b2 -> global ----
    {
        float acc[4][4];
        #pragma unroll
        for (int i = 0; i < 4; i++)
            #pragma unroll
            for (int j = 0; j < 4; j++) acc[i][j] = 0.0f;

        mma_gemm64<8, QKV_STR>(Qf, W2, acc, mtile, nhalf, g, tq);

        #pragma unroll
        for (int nt = 0; nt < 4; nt++) {
            int j0 = nhalf * 32 + nt * 8 + 2 * tq;
            float bj0 = b2[j0], bj1 = b2[j0 + 1];
            int r0 = mtile * 16 + g;
            float* o0 = out + (((size_t)b * T_ + r0)     * N_ + n) * D_ + j0;
            float* o1 = out + (((size_t)b * T_ + r0 + 8) * N_ + n) * D_ + j0;
            o0[0] = acc[nt][0] + bj0;
            o0[1] = acc[nt][1] + bj1;
            o1[0] = acc[nt][2] + bj0;
            o1[1] = acc[nt][3] + bj1;
        }
    }
}

extern "C" void kernel_launch(void* const* d_in, const int* in_sizes, int n_in,
                              void* d_out, int out_size)
{
    (void)in_sizes; (void)n_in; (void)out_size;
    const float* x   = (const float*)d_in[0];
    const float* ste = (const float*)d_in[1];
    const float* Wq  = (const float*)d_in[2];
    const float* bq  = (const float*)d_in[3];
    const float* Wk  = (const float*)d_in[4];
    const float* bk  = (const float*)d_in[5];
    const float* Wv  = (const float*)d_in[6];
    const float* bv  = (const float*)d_in[7];
    const float* W1  = (const float*)d_in[8];
    const float* b1  = (const float*)d_in[9];
    const float* W2  = (const float*)d_in[10];
    const float* b2  = (const float*)d_in[11];
    float* out = (float*)d_out;

    const int smem_bytes = SMEM_FLOATS * sizeof(float);   // 206848
    static bool attr_set = false;
    if (!attr_set) {
        cudaFuncSetAttribute(temporal_attn_kernel,
                             cudaFuncAttributeMaxDynamicSharedMemorySize,
                             smem_bytes);
        attr_set = true;
    }
    temporal_attn_kernel<<<(B_ * N_) / 2, 512, smem_bytes>>>(
        x, ste, Wq, bq, Wk, bk, Wv, bv, W1, b1, W2, b2, out);
}